// round 8
// baseline (speedup 1.0000x reference)
#include <cuda_runtime.h>

// DynamicLinearModel: out[r,t] = theta[r,t] + X[t]·eta[r] + Z[t]·zeta[r]
//   theta_{t+1} = a_r*theta_t + b_t,  b_t = Z[t]·gamma[r],  a_r = sigmoid(G[r]), theta_0=0
// R=4096, T=2048, XD=ZD=8.
//
// R6 design (resubmitted after infra flake): register/latency-bound fix.
//  - 4 rows per warp via 8-lane octets sharing X/Z loads (broadcast LDS) ->
//    per-lane weights = 1 row (24 regs), LDS bytes unchanged per warp count.
//  - T split into 4 quarters per row-quad -> 4096 warp tasks, 28 warps/SM.
//  - Each quarter sweeps with carry C=0, stores, publishes local carry to smem;
//    after syncthreads, quarters q>0 add the exact a^Delta * theta(512q)
//    correction via float4 RMW (linear recurrence => exact).
//  - Chunks of 32 t: lane o owns t=4o..4o+3; width-8 shuffle scan (mult a^4).
//  - Stores: 8 lanes x 16B contiguous per row -> 4 full lines per STG.128.

#define T_DIM 2048
#define R_DIM 4096
#define NWARP 28
#define NT (NWARP * 32)                  // 896
#define QPC 7                            // row-quads per CTA
#define NQUAD (R_DIM / 4)                // 1024
#define GRID ((NQUAD + QPC - 1) / QPC)   // 147
#define QT 512                           // t per quarter
#define CHT 32                           // t per chunk
#define NCH (QT / CHT)                   // 16
#define SLAB_BYTES 65536
#define SMEM_BYTES (2 * SLAB_BYTES + QPC * 4 * 4 * 4)

__device__ __forceinline__ unsigned long long ffma2(unsigned long long x,
                                                    unsigned long long w,
                                                    unsigned long long c) {
    unsigned long long d;
    asm("fma.rn.f32x2 %0, %1, %2, %3;" : "=l"(d) : "l"(x), "l"(w), "l"(c));
    return d;
}
__device__ __forceinline__ unsigned long long pack2(float lo, float hi) {
    unsigned long long d;
    asm("mov.b64 %0, {%1, %2};" : "=l"(d) : "f"(lo), "f"(hi));
    return d;
}
__device__ __forceinline__ float hsum2(unsigned long long v) {
    float lo, hi;
    asm("mov.b64 {%0, %1}, %2;" : "=f"(lo), "=f"(hi) : "l"(v));
    return lo + hi;
}
// XOR-128 swizzle on byte offsets: with lane mapping t=4o+k, quad=(2k+h)^o,
// conflict-free across octets, broadcast across row-groups.
__device__ __forceinline__ int swz(int ob) {
    return ob ^ (((ob >> 7) & 7) << 4);
}

union F4U { float4 f; unsigned long long u[2]; };

__global__ void __launch_bounds__(NT, 1)
dlm_kernel(const float* __restrict__ X, const float* __restrict__ Z,
           const float* __restrict__ G, const float* __restrict__ eta,
           const float* __restrict__ zeta, const float* __restrict__ gamma,
           float* __restrict__ out)
{
    extern __shared__ char sm[];
    char* Xs = sm;
    char* Zs = sm + SLAB_BYTES;
    float* Ct = (float*)(sm + 2 * SLAB_BYTES);   // [QPC*4 rows][4 quarters]

    const int tid  = threadIdx.x;
    const int w    = tid >> 5;
    const int lane = tid & 31;
    const int o    = lane & 7;       // octet lane (t position)
    const int rowo = lane >> 3;      // row within quad (0..3)

    // ---- cooperative swizzled slab load ----
    for (int v = tid; v < T_DIM * 2; v += NT) {
        int po = swz(v * 16);
        *(float4*)(Xs + po) = ((const float4*)X)[v];
        *(float4*)(Zs + po) = ((const float4*)Z)[v];
    }
    __syncthreads();

    const int quadIdx = w >> 2;              // 0..6
    const int q       = w & 3;               // T-quarter 0..3
    const int quad    = blockIdx.x * QPC + quadIdx;
    const bool active = (quad < NQUAD);

    float a = 0.f, a2_ = 0.f, a3_ = 0.f, a4 = 0.f, a8 = 0.f, a16 = 0.f,
          a32 = 0.f, pa4o = 0.f, C = 0.f;
    F4U e0, e1, s0, s1, g0, g1;
    float* outp = out;

    if (active) {
        int r = quad * 4 + rowo;
        a = 1.0f / (1.0f + expf(-G[r]));
        e0.f = *(const float4*)(eta   + r * 8);
        e1.f = *(const float4*)(eta   + r * 8 + 4);
        s0.f = *(const float4*)(zeta  + r * 8);
        s1.f = *(const float4*)(zeta  + r * 8 + 4);
        g0.f = *(const float4*)(gamma + r * 8);
        g1.f = *(const float4*)(gamma + r * 8 + 4);
        a2_ = a * a;  a3_ = a2_ * a;  a4 = a2_ * a2_;
        a8 = a4 * a4;  a16 = a8 * a8;  a32 = a16 * a16;
        // pa4o = a^(4*o)
        float p = a4, v = 1.0f;
        if (o & 1) v *= p;  p *= p;
        if (o & 2) v *= p;  p *= p;
        if (o & 4) v *= p;
        pa4o = v;
        outp = out + (size_t)r * T_DIM + q * QT + 4 * o;

        // ---- sweep 16 chunks of 32 t (carry starts at 0 for this quarter) ----
        for (int c = 0; c < NCH; c++) {
            const int t0 = q * QT + c * CHT + 4 * o;
            float b[4], d[4];
            #pragma unroll
            for (int k = 0; k < 4; k++) {
                int ob = (t0 + k) * 32;
                F4U x0, x1, z0, z1;
                x0.f = *(const float4*)(Xs + swz(ob));
                x1.f = *(const float4*)(Xs + swz(ob + 16));
                z0.f = *(const float4*)(Zs + swz(ob));
                z1.f = *(const float4*)(Zs + swz(ob + 16));

                unsigned long long bb = ffma2(z0.u[0], g0.u[0], pack2(0.f, 0.f));
                bb = ffma2(z0.u[1], g0.u[1], bb);
                bb = ffma2(z1.u[0], g1.u[0], bb);
                bb = ffma2(z1.u[1], g1.u[1], bb);
                b[k] = hsum2(bb);

                unsigned long long xz = ffma2(x0.u[0], e0.u[0], pack2(0.f, 0.f));
                xz = ffma2(x0.u[1], e0.u[1], xz);
                xz = ffma2(x1.u[0], e1.u[0], xz);
                xz = ffma2(x1.u[1], e1.u[1], xz);
                xz = ffma2(z0.u[0], s0.u[0], xz);
                xz = ffma2(z0.u[1], s0.u[1], xz);
                xz = ffma2(z1.u[0], s1.u[0], xz);
                xz = ffma2(z1.u[1], s1.u[1], xz);
                d[k] = hsum2(xz);
            }
            // local combine: wv = a^3 b0 + a^2 b1 + a b2 + b3
            float wv = fmaf(fmaf(fmaf(b[0], a, b[1]), a, b[2]), a, b[3]);
            // width-8 inclusive scan, multiplier a^4
            float s = wv, up;
            up = __shfl_up_sync(0xffffffffu, s, 1, 8); if (o >= 1) s = fmaf(a4,  up, s);
            up = __shfl_up_sync(0xffffffffu, s, 2, 8); if (o >= 2) s = fmaf(a8,  up, s);
            up = __shfl_up_sync(0xffffffffu, s, 4, 8); if (o >= 4) s = fmaf(a16, up, s);
            float E = __shfl_up_sync(0xffffffffu, s, 1, 8);
            if (o == 0) E = 0.0f;
            float W = __shfl_sync(0xffffffffu, s, 7, 8);

            float th = fmaf(pa4o, C, E);
            C = fmaf(a32, C, W);

            float4 ov;
            ov.x = th + d[0];  th = fmaf(a, th, b[0]);
            ov.y = th + d[1];  th = fmaf(a, th, b[1]);
            ov.z = th + d[2];  th = fmaf(a, th, b[2]);
            ov.w = th + d[3];
            *(float4*)(outp + c * CHT) = ov;
        }
        // publish this quarter's local carry (identical across octet lanes)
        if (o == 0)
            Ct[(quadIdx * 4 + rowo) * 4 + q] = C;
    }
    __syncthreads();

    // ---- correction: add exact a^Delta * theta(512q) to quarters q>0 ----
    if (active && q > 0) {
        float a64  = a32 * a32;
        float a128 = a64 * a64;
        float a256 = a128 * a128;
        float a512 = a256 * a256;
        float Ccum = 0.0f;
        for (int i = 0; i < q; i++)
            Ccum = fmaf(Ccum, a512, Ct[(quadIdx * 4 + rowo) * 4 + i]);

        float fa = Ccum * pa4o;      // decay factor at this lane's first t
        for (int c = 0; c < NCH; c++) {
            float4 v = *(float4*)(outp + c * CHT);
            v.x += fa;
            v.y = fmaf(fa, a,   v.y);
            v.z = fmaf(fa, a2_, v.z);
            v.w = fmaf(fa, a3_, v.w);
            *(float4*)(outp + c * CHT) = v;
            fa *= a32;
        }
    }
}

extern "C" void kernel_launch(void* const* d_in, const int* in_sizes, int n_in,
                              void* d_out, int out_size) {
    const float* X     = (const float*)d_in[0];
    const float* Z     = (const float*)d_in[1];
    const float* G     = (const float*)d_in[2];
    const float* eta   = (const float*)d_in[3];
    const float* zeta  = (const float*)d_in[4];
    const float* gamma = (const float*)d_in[5];
    float* out = (float*)d_out;

    cudaFuncSetAttribute(dlm_kernel,
                         cudaFuncAttributeMaxDynamicSharedMemorySize, SMEM_BYTES);
    dlm_kernel<<<GRID, NT, SMEM_BYTES>>>(X, Z, G, eta, zeta, gamma, out);
}

// round 9
// speedup vs baseline: 1.4914x; 1.4914x over previous
#include <cuda_runtime.h>

// DynamicLinearModel: out[r,t] = theta[r,t] + X[t]·eta[r] + Z[t]·zeta[r]
//   theta_{t+1} = a_r*theta_t + b_t,  b_t = Z[t]·gamma[r],  a_r = sigmoid(G[r]), theta_0=0
// R=4096, T=2048, XD=ZD=8.
//
// R8 design: R4 (best: 22.0us) refined.
//  - warp owns 2 rows x full T; 16 chunks of 128 t; carry in register.
//  - prefix-fold: dp[k] = d_k + lp_k with lp = a*lp + b_k; out_k = a^k*th0 + dp[k].
//    Removes b[] regs, local combine, replay fmas.
//  - hoisted swizzle: XOR term (lane&7)<<4 is per-thread constant; 8 precomputed
//    offsets; chunk base += 4096 (swizzle-invariant).
//  - unroll 2 on chunk loop: next chunk's LDS/dot chains overlap current scan.
//  - X/Z in 128KB XOR-swizzled SMEM slab; float4 stores lanes-contiguous in t.
//  - grid 148 x 14 warps = 2072 warps covering 2048 row-pairs.

#define T_DIM 2048
#define R_DIM 4096
#define RPT 2
#define NWARP 14
#define NT (NWARP * 32)          // 448
#define NPAIR (R_DIM / RPT)      // 2048
#define GRID 148
#define CHT 128                  // t per chunk
#define NCH (T_DIM / CHT)        // 16
#define SLAB_BYTES 65536
#define SMEM_BYTES (2 * SLAB_BYTES)

__device__ __forceinline__ unsigned long long ffma2(unsigned long long x,
                                                    unsigned long long w,
                                                    unsigned long long c) {
    unsigned long long d;
    asm("fma.rn.f32x2 %0, %1, %2, %3;" : "=l"(d) : "l"(x), "l"(w), "l"(c));
    return d;
}
__device__ __forceinline__ unsigned long long pack2(float lo, float hi) {
    unsigned long long d;
    asm("mov.b64 %0, {%1, %2};" : "=l"(d) : "f"(lo), "f"(hi));
    return d;
}
__device__ __forceinline__ float hsum2(unsigned long long v) {
    float lo, hi;
    asm("mov.b64 {%0, %1}, %2;" : "=f"(lo), "=f"(hi) : "l"(v));
    return lo + hi;
}
// Full swizzle (slab fill only): XOR bits[4:6] with bits[7:9].
__device__ __forceinline__ int swz(int ob) {
    return ob ^ (((ob >> 7) & 7) << 4);
}

union F4U { float4 f; unsigned long long u[2]; };

__global__ void __launch_bounds__(NT, 1)
dlm_kernel(const float* __restrict__ X, const float* __restrict__ Z,
           const float* __restrict__ G, const float* __restrict__ eta,
           const float* __restrict__ zeta, const float* __restrict__ gamma,
           float* __restrict__ out)
{
    extern __shared__ char sm[];
    char* Xs = sm;
    char* Zs = sm + SLAB_BYTES;

    const int tid  = threadIdx.x;
    const int w    = tid >> 5;
    const int lane = tid & 31;

    // ---- cooperative swizzled slab load ----
    for (int v = tid; v < T_DIM * 2; v += NT) {
        int po = swz(v * 16);
        *(float4*)(Xs + po) = ((const float4*)X)[v];
        *(float4*)(Zs + po) = ((const float4*)Z)[v];
    }
    __syncthreads();

    const int pair = w * GRID + blockIdx.x;
    if (pair >= NPAIR) return;
    const int r0 = pair * RPT;

    // In-sweep addresses: ob = cb + lane*128 + k*32 + h*16, with cb % 4096 == 0
    // -> bits[7:9] of ob == lane&7 -> XOR term constant. Precompute combined
    // (k,h) offsets; per-chunk just advance the lane base by 4096.
    const int xort = (lane & 7) << 4;
    int off[4][2];
    #pragma unroll
    for (int k = 0; k < 4; k++) {
        off[k][0] = (k * 32) ^ xort;
        off[k][1] = (k * 32 + 16) ^ xort;
    }

    // ---- per-row constants ----
    F4U e0[RPT], e1[RPT], s0[RPT], s1[RPT], g0[RPT], g1[RPT];
    float a[RPT], a2_[RPT], a3_[RPT],
          m0[RPT], m1[RPT], m2[RPT], m3[RPT], m4[RPT],
          a128[RPT], pa4l[RPT], C[RPT];
    #pragma unroll
    for (int j = 0; j < RPT; j++) {
        int r = r0 + j;
        a[j] = 1.0f / (1.0f + expf(-G[r]));
        e0[j].f = *(const float4*)(eta   + r * 8);
        e1[j].f = *(const float4*)(eta   + r * 8 + 4);
        s0[j].f = *(const float4*)(zeta  + r * 8);
        s1[j].f = *(const float4*)(zeta  + r * 8 + 4);
        g0[j].f = *(const float4*)(gamma + r * 8);
        g1[j].f = *(const float4*)(gamma + r * 8 + 4);
        a2_[j] = a[j] * a[j];
        a3_[j] = a2_[j] * a[j];
        m0[j] = a2_[j] * a2_[j];       // a^4
        m1[j] = m0[j] * m0[j];
        m2[j] = m1[j] * m1[j];
        m3[j] = m2[j] * m2[j];
        m4[j] = m3[j] * m3[j];
        a128[j] = m4[j] * m4[j];
        float p = m0[j], v = 1.0f;     // a^(4*lane)
        #pragma unroll
        for (int k = 0; k < 5; k++) {
            if (lane & (1 << k)) v *= p;
            p *= p;
        }
        pa4l[j] = v;
        C[j] = 0.0f;
    }

    float* outp = out + (size_t)r0 * T_DIM + 4 * lane;
    int lb = lane * 128;               // swizzled lane base within chunk

    // ---- serial sweep over 16 chunks of 128 t ----
    #pragma unroll 2
    for (int c = 0; c < NCH; c++) {
        // Phase 1: transient loads -> dp[k] = d_k + lp_k ; lp = a*lp + b_k
        float dp[RPT][4];
        float lp[RPT];
        #pragma unroll
        for (int j = 0; j < RPT; j++) lp[j] = 0.0f;

        #pragma unroll
        for (int k = 0; k < 4; k++) {
            F4U x0, x1, z0, z1;
            x0.f = *(const float4*)(Xs + lb + off[k][0]);
            x1.f = *(const float4*)(Xs + lb + off[k][1]);
            z0.f = *(const float4*)(Zs + lb + off[k][0]);
            z1.f = *(const float4*)(Zs + lb + off[k][1]);
            #pragma unroll
            for (int j = 0; j < RPT; j++) {
                unsigned long long bb = ffma2(z0.u[0], g0[j].u[0], pack2(0.f, 0.f));
                bb = ffma2(z0.u[1], g0[j].u[1], bb);
                bb = ffma2(z1.u[0], g1[j].u[0], bb);
                bb = ffma2(z1.u[1], g1[j].u[1], bb);
                float b = hsum2(bb);

                unsigned long long xz = ffma2(x0.u[0], e0[j].u[0], pack2(0.f, 0.f));
                xz = ffma2(x0.u[1], e0[j].u[1], xz);
                xz = ffma2(x1.u[0], e1[j].u[0], xz);
                xz = ffma2(x1.u[1], e1[j].u[1], xz);
                xz = ffma2(z0.u[0], s0[j].u[0], xz);
                xz = ffma2(z0.u[1], s0[j].u[1], xz);
                xz = ffma2(z1.u[0], s1[j].u[0], xz);
                xz = ffma2(z1.u[1], s1[j].u[1], xz);

                dp[j][k] = hsum2(xz) + lp[j];
                lp[j] = fmaf(a[j], lp[j], b);
            }
        }
        lb += 4096;                    // next chunk (swizzle-invariant stride)

        // Phase 2: per-row warp scan (mult a^4) + outputs
        #pragma unroll
        for (int j = 0; j < RPT; j++) {
            float s = lp[j], up;
            up = __shfl_up_sync(0xffffffffu, s, 1);  if (lane >= 1)  s = fmaf(m0[j], up, s);
            up = __shfl_up_sync(0xffffffffu, s, 2);  if (lane >= 2)  s = fmaf(m1[j], up, s);
            up = __shfl_up_sync(0xffffffffu, s, 4);  if (lane >= 4)  s = fmaf(m2[j], up, s);
            up = __shfl_up_sync(0xffffffffu, s, 8);  if (lane >= 8)  s = fmaf(m3[j], up, s);
            up = __shfl_up_sync(0xffffffffu, s, 16); if (lane >= 16) s = fmaf(m4[j], up, s);
            float E = __shfl_up_sync(0xffffffffu, s, 1);
            if (lane == 0) E = 0.0f;
            float W = __shfl_sync(0xffffffffu, s, 31);

            float th = fmaf(pa4l[j], C[j], E);
            C[j] = fmaf(a128[j], C[j], W);

            float4 ov;
            ov.x = th + dp[j][0];
            ov.y = fmaf(a[j],   th, dp[j][1]);
            ov.z = fmaf(a2_[j], th, dp[j][2]);
            ov.w = fmaf(a3_[j], th, dp[j][3]);
            *(float4*)(outp + (size_t)j * T_DIM + c * CHT) = ov;
        }
    }
}

extern "C" void kernel_launch(void* const* d_in, const int* in_sizes, int n_in,
                              void* d_out, int out_size) {
    const float* X     = (const float*)d_in[0];
    const float* Z     = (const float*)d_in[1];
    const float* G     = (const float*)d_in[2];
    const float* eta   = (const float*)d_in[3];
    const float* zeta  = (const float*)d_in[4];
    const float* gamma = (const float*)d_in[5];
    float* out = (float*)d_out;

    cudaFuncSetAttribute(dlm_kernel,
                         cudaFuncAttributeMaxDynamicSharedMemorySize, SMEM_BYTES);
    dlm_kernel<<<GRID, NT, SMEM_BYTES>>>(X, Z, G, eta, zeta, gamma, out);
}